// round 1
// baseline (speedup 1.0000x reference)
#include <cuda_runtime.h>
#include <cuda_bf16.h>
#include <stdint.h>

// Problem constants (fixed shapes)
#define NLAT_IN   181
#define NLON_IN   360
#define NLAT_OUT  361
#define NLON_OUT  720
#define KSIZE     3
#define CIN       16
#define COUT      16
#define NNZ_MAX   8192

#define X_CI_STRIDE   (NLAT_IN * NLON_IN)         // 65160
#define XW_CO_STRIDE  (KSIZE * NLAT_IN * NLON_IN) // 195480
#define NBINS         (NLAT_OUT * 2)              // 722 (lat, parity)
#define OUT_ROW       NLON_OUT

// Scratch (device globals; no dynamic allocation allowed)
__device__ float g_xw[COUT * KSIZE * NLAT_IN * NLON_IN]; // 12.5 MB, L2-resident
__device__ int   g_count[NBINS];
__device__ int   g_starts[NBINS + 2];
__device__ int   g_cursor[NBINS];
__device__ int2  g_entries[NNZ_MAX];   // .x = base(18b) | shift<<18 ; .y = bits(val)

__constant__ float c_weight[COUT * CIN * KSIZE]; // 768
__constant__ float c_bias[COUT];

// ---------------------------------------------------------------------------
// K0: zero bin counts
__global__ void zero_counts_kernel() {
    int t = blockIdx.x * blockDim.x + threadIdx.x;
    if (t < NBINS) g_count[t] = 0;
}

// K1: histogram of nnz by (out_lat, parity(p))
__global__ void count_kernel(const int* __restrict__ col_idx, int nnz) {
    int i = blockIdx.x * blockDim.x + threadIdx.x;
    if (i >= nnz) return;
    int col = col_idx[i];
    int hi  = col / NLON_OUT;
    int par = col & 1;             // NLON_OUT is even, so p parity == col parity
    atomicAdd(&g_count[hi * 2 + par], 1);
}

// K2: exclusive scan of 722 counts (single block Hillis-Steele), writes cursors
__global__ void scan_kernel() {
    __shared__ int buf[1024];
    int t = threadIdx.x;
    int v = (t < NBINS) ? g_count[t] : 0;
    buf[t] = v;
    __syncthreads();
    #pragma unroll
    for (int off = 1; off < 1024; off <<= 1) {
        int add = (t >= off) ? buf[t - off] : 0;
        __syncthreads();
        buf[t] += add;
        __syncthreads();
    }
    if (t < NBINS) {
        g_starts[t + 1] = buf[t];       // inclusive -> starts[t+1]
        g_cursor[t]     = buf[t] - v;   // exclusive prefix = bin start
    }
    if (t == 0) g_starts[0] = 0;
}

// K3: fill binned entries (packed)
__global__ void fill_kernel(const int* __restrict__ ker_idx,
                            const int* __restrict__ row_idx,
                            const int* __restrict__ col_idx,
                            const float* __restrict__ vals, int nnz) {
    int i = blockIdx.x * blockDim.x + threadIdx.x;
    if (i >= nnz) return;
    int col = col_idx[i];
    int hi  = col / NLON_OUT;
    int p   = col - hi * NLON_OUT;
    int key = hi * 2 + (p & 1);
    int pos = atomicAdd(&g_cursor[key], 1);
    int k   = ker_idx[i];
    int tin = row_idx[i];
    int base  = (k * NLAT_IN + tin) * NLON_IN;   // < 2^18
    int shift = p >> 1;                           // < 512
    g_entries[pos] = make_int2(base | (shift << 18), __float_as_int(vals[i]));
}

// K4: channel-mix einsum xw[co,k,tin,po] = sum_ci w[co,ci,k] * x[ci,tin,po]
// grid (NLAT_IN, 4 co-groups), 384 threads (t<360 active, t = po)
__global__ __launch_bounds__(384) void einsum_kernel(const float* __restrict__ x) {
    int tin = blockIdx.x;
    int co0 = blockIdx.y * 4;
    int t   = threadIdx.x;
    if (t >= NLON_IN) return;

    const float* xp = x + tin * NLON_IN + t;
    float xv[CIN];
    #pragma unroll
    for (int ci = 0; ci < CIN; ci++) xv[ci] = __ldg(xp + ci * X_CI_STRIDE);

    float acc[12];
    #pragma unroll
    for (int j = 0; j < 12; j++) acc[j] = 0.0f;

    #pragma unroll
    for (int ci = 0; ci < CIN; ci++) {
        float xvv = xv[ci];
        #pragma unroll
        for (int cc = 0; cc < 4; cc++) {
            #pragma unroll
            for (int k = 0; k < KSIZE; k++) {
                acc[cc * 3 + k] = fmaf(c_weight[((co0 + cc) * CIN + ci) * KSIZE + k],
                                       xvv, acc[cc * 3 + k]);
            }
        }
    }
    #pragma unroll
    for (int cc = 0; cc < 4; cc++) {
        #pragma unroll
        for (int k = 0; k < KSIZE; k++) {
            g_xw[(((co0 + cc) * KSIZE + k) * NLAT_IN + tin) * NLON_IN + t] = acc[cc * 3 + k];
        }
    }
}

// K5: gather kernel — one thread owns output lons (2t) and (2t+1) for one
// output latitude, accumulating over that row's binned nonzeros in registers.
// grid (NLAT_OUT, 4 co-groups), 384 threads (t<360 active)
__global__ __launch_bounds__(384) void gather_kernel(float* __restrict__ out) {
    int ho  = blockIdx.x;
    int cg  = blockIdx.y;
    int t   = threadIdx.x;
    if (t >= NLON_IN) return;

    int s0 = g_starts[2 * ho];
    int s1 = g_starts[2 * ho + 1];
    int s2 = g_starts[2 * ho + 2];

    const float* xw = g_xw + cg * 4 * XW_CO_STRIDE;

    float aE0 = 0.f, aE1 = 0.f, aE2 = 0.f, aE3 = 0.f;
    float aO0 = 0.f, aO1 = 0.f, aO2 = 0.f, aO3 = 0.f;

    // even-parity entries contribute to wo = 2t
    for (int i = s0; i < s1; i++) {
        int2 e = g_entries[i];
        int shift = ((unsigned)e.x) >> 18;
        int base  = e.x & 0x3FFFF;
        float v   = __int_as_float(e.y);
        int idx = t - shift; if (idx < 0) idx += NLON_IN;
        const float* p = xw + base + idx;
        aE0 = fmaf(v, __ldg(p),                    aE0);
        aE1 = fmaf(v, __ldg(p +     XW_CO_STRIDE), aE1);
        aE2 = fmaf(v, __ldg(p + 2 * XW_CO_STRIDE), aE2);
        aE3 = fmaf(v, __ldg(p + 3 * XW_CO_STRIDE), aE3);
    }
    // odd-parity entries contribute to wo = 2t+1
    for (int i = s1; i < s2; i++) {
        int2 e = g_entries[i];
        int shift = ((unsigned)e.x) >> 18;
        int base  = e.x & 0x3FFFF;
        float v   = __int_as_float(e.y);
        int idx = t - shift; if (idx < 0) idx += NLON_IN;
        const float* p = xw + base + idx;
        aO0 = fmaf(v, __ldg(p),                    aO0);
        aO1 = fmaf(v, __ldg(p +     XW_CO_STRIDE), aO1);
        aO2 = fmaf(v, __ldg(p + 2 * XW_CO_STRIDE), aO2);
        aO3 = fmaf(v, __ldg(p + 3 * XW_CO_STRIDE), aO3);
    }

    int co0 = cg * 4;
    float2* orow;
    float b;

    b = c_bias[co0 + 0];
    orow = (float2*)(out + (size_t)(co0 + 0) * (NLAT_OUT * NLON_OUT) + ho * OUT_ROW);
    orow[t] = make_float2(aE0 + b, aO0 + b);
    b = c_bias[co0 + 1];
    orow = (float2*)(out + (size_t)(co0 + 1) * (NLAT_OUT * NLON_OUT) + ho * OUT_ROW);
    orow[t] = make_float2(aE1 + b, aO1 + b);
    b = c_bias[co0 + 2];
    orow = (float2*)(out + (size_t)(co0 + 2) * (NLAT_OUT * NLON_OUT) + ho * OUT_ROW);
    orow[t] = make_float2(aE2 + b, aO2 + b);
    b = c_bias[co0 + 3];
    orow = (float2*)(out + (size_t)(co0 + 3) * (NLAT_OUT * NLON_OUT) + ho * OUT_ROW);
    orow[t] = make_float2(aE3 + b, aO3 + b);
}

// ---------------------------------------------------------------------------
extern "C" void kernel_launch(void* const* d_in, const int* in_sizes, int n_in,
                              void* d_out, int out_size) {
    const float* x       = (const float*)d_in[0];
    const float* weight  = (const float*)d_in[1];
    const float* bias    = (const float*)d_in[2];
    const int*   ker_idx = (const int*)d_in[3];
    const int*   row_idx = (const int*)d_in[4];
    const int*   col_idx = (const int*)d_in[5];
    const float* vals    = (const float*)d_in[6];
    float* out = (float*)d_out;

    int nnz = in_sizes[3];
    if (nnz > NNZ_MAX) nnz = NNZ_MAX;

    cudaMemcpyToSymbolAsync(c_weight, weight, COUT * CIN * KSIZE * sizeof(float),
                            0, cudaMemcpyDeviceToDevice, 0);
    cudaMemcpyToSymbolAsync(c_bias, bias, COUT * sizeof(float),
                            0, cudaMemcpyDeviceToDevice, 0);

    zero_counts_kernel<<<(NBINS + 255) / 256, 256>>>();
    count_kernel<<<(nnz + 255) / 256, 256>>>(col_idx, nnz);
    scan_kernel<<<1, 1024>>>();
    fill_kernel<<<(nnz + 255) / 256, 256>>>(ker_idx, row_idx, col_idx, vals, nnz);

    dim3 egrid(NLAT_IN, 4);
    einsum_kernel<<<egrid, 384>>>(x);

    dim3 ggrid(NLAT_OUT, 4);
    gather_kernel<<<ggrid, 384>>>(out);
}